// round 13
// baseline (speedup 1.0000x reference)
#include <cuda_runtime.h>
#include <cuda_bf16.h>

// Inputs (metadata order):
//   0: shape    float32 [B, C, H, W]       B=16, C=128, H=W=128
//   1: size     int32   scalar (S=1024)
//   2: saliency float32 [B, 1, H, W]       (unused)
//   3: mask     int32   [B, K]             K=256
//   4: ind      int32   [B, K]
//   5: target   float32 [B, K, S]
// Output: float32 [1] = sum(|pred*m - target*m|) / (sum(m)*S + 1e-4)
//
// Persistent software-pipelined kernel: NB resident blocks, each block
// iterates over groups of P=4 pairs. Data for stage g+1 (target float4s +
// gather loads) is issued while stage g computes; mask/ind metadata is
// prefetched two stages ahead to hide the ind->gather dependent chain.

__device__ float        g_loss_acc;   // zero-init; reset by last block
__device__ int          g_mask_cnt;
__device__ unsigned int g_done;

__device__ __forceinline__ void finalize_and_reset(float* __restrict__ out,
                                                   int S, int nBlocks)
{
    __threadfence();
    unsigned int ticket = atomicAdd(&g_done, 1u);
    if (ticket == (unsigned int)(nBlocks - 1)) {
        float total = atomicAdd(&g_loss_acc, 0.0f);
        int   cnt   = atomicAdd(&g_mask_cnt, 0);
        out[0] = total / ((float)cnt * (float)S + 1e-4f);
        g_loss_acc = 0.0f;
        g_mask_cnt = 0;
        __threadfence();
        g_done = 0u;
    }
}

// ---- stage macros (plain code so everything stays in registers) ----
#define LOAD_META(g, m, hwv, bv)                                              \
    {                                                                         \
        _Pragma("unroll")                                                     \
        for (int p = 0; p < P; p++)                                           \
            m[p] = ((g) < G) ? mask[(g) * P + p] : 0;                         \
        _Pragma("unroll")                                                     \
        for (int j = 0; j < 2; j++) {                                         \
            const int p = pA + 2 * j;                                         \
            if ((g) < G && m[p]) {                                            \
                const int bk = (g) * P + p;                                   \
                bv[j]  = bk / K;                                              \
                hwv[j] = ind[bk];                                             \
            }                                                                 \
        }                                                                     \
    }

#define ISSUE_DATA(g, m, hwv, bv, tv, gv)                                     \
    {                                                                         \
        if ((g) < G) {                                                        \
            _Pragma("unroll")                                                 \
            for (int p = 0; p < P; p++)                                       \
                if (m[p])                                                     \
                    tv[p] = __ldg(((const float4*)(target +                   \
                              (size_t)((g) * P + p) * S)) + t);               \
            _Pragma("unroll")                                                 \
            for (int j = 0; j < 2; j++) {                                     \
                const int p = pA + 2 * j;                                     \
                if (m[p])                                                     \
                    gv[j] = __ldg(&shape[(size_t)bv[j] * C * HW +             \
                                         (size_t)cA * HW + hwv[j]]);          \
            }                                                                 \
        }                                                                     \
    }

// ---------------- specialized persistent: C=128, S=1024 ----------------
__global__ void __launch_bounds__(256) ml_persist_kernel(
    const float* __restrict__ shape,   // [B, C, HW]
    const int*   __restrict__ mask,    // [B*K]
    const int*   __restrict__ ind,     // [B*K]
    const float* __restrict__ target,  // [B*K, S]
    float*       __restrict__ out,
    int HW, int K, int G)              // G = nPairs/P groups
{
    constexpr int C = 128, S = 1024, P = 4;
    const int t  = threadIdx.x;        // 0..255
    const int cA = t & 127;            // channel this thread gathers
    const int pA = t >> 7;             // gathers pairs pA and pA+2
    const int NB = gridDim.x;

    __shared__ float pred[2][P][C];    // double buffer: 4KB
    __shared__ float warp_sums[8];

    // ---- interp coefficients: fixed per thread (s = 4t..4t+3) ----
    const float scale = (float)C / (float)S;
    const float cmax  = (float)(C - 1);
    int   lo[4], hi[4];
    float w[4];
    #pragma unroll
    for (int j = 0; j < 4; j++) {
        float pos = ((float)(4 * t + j) + 0.5f) * scale - 0.5f;
        pos = fminf(fmaxf(pos, 0.0f), cmax);
        lo[j] = (int)pos;
        hi[j] = min(lo[j] + 1, C - 1);
        w[j]  = pos - (float)lo[j];
    }

    // ---- pipeline state ----
    int    m_cur[P], m_nxt[P];
    int    hw_cur[2], hw_nxt[2], b_cur[2], b_nxt[2];
    float4 tv_cur[P], tv_nxt[P];
    float  gv_cur[2], gv_nxt[2];

    int g = blockIdx.x;
    LOAD_META(g, m_cur, hw_cur, b_cur);
    LOAD_META(g + NB, m_nxt, hw_nxt, b_nxt);
    ISSUE_DATA(g, m_cur, hw_cur, b_cur, tv_cur, gv_cur);

    float acc = 0.0f;
    int   cnt = 0;
    int   buf = 0;

    for (; g < G; g += NB, buf ^= 1) {
        const int gn  = g + NB;
        const int gnn = g + 2 * NB;

        // Prefetch: data for next stage, meta for stage after that.
        ISSUE_DATA(gn, m_nxt, hw_nxt, b_nxt, tv_nxt, gv_nxt);
        int m_nn[P], hw_nn[2], b_nn[2];
        LOAD_META(gnn, m_nn, hw_nn, b_nn);

        // Stage current gathers into smem (loads were issued last iteration).
        #pragma unroll
        for (int j = 0; j < 2; j++) {
            const int p = pA + 2 * j;
            if (m_cur[p]) pred[buf][p][cA] = gv_cur[j];
        }
        __syncthreads();

        // Compute current stage from registers + smem.
        #pragma unroll
        for (int p = 0; p < P; p++) {
            if (m_cur[p]) {
                const float* pr = pred[buf][p];
                acc += fabsf(pr[lo[0]] * (1.0f - w[0]) + pr[hi[0]] * w[0] - tv_cur[p].x);
                acc += fabsf(pr[lo[1]] * (1.0f - w[1]) + pr[hi[1]] * w[1] - tv_cur[p].y);
                acc += fabsf(pr[lo[2]] * (1.0f - w[2]) + pr[hi[2]] * w[2] - tv_cur[p].z);
                acc += fabsf(pr[lo[3]] * (1.0f - w[3]) + pr[hi[3]] * w[3] - tv_cur[p].w);
            }
        }
        cnt += m_cur[0] + m_cur[1] + m_cur[2] + m_cur[3];

        // Rotate pipeline registers.
        #pragma unroll
        for (int p = 0; p < P; p++) {
            m_cur[p]  = m_nxt[p];
            tv_cur[p] = tv_nxt[p];
            m_nxt[p]  = m_nn[p];
        }
        #pragma unroll
        for (int j = 0; j < 2; j++) {
            hw_cur[j] = hw_nxt[j]; b_cur[j] = b_nxt[j]; gv_cur[j] = gv_nxt[j];
            hw_nxt[j] = hw_nn[j];  b_nxt[j] = b_nn[j];
        }
    }

    // ---- block reduction over 8 warps ----
    #pragma unroll
    for (int off = 16; off > 0; off >>= 1)
        acc += __shfl_down_sync(0xFFFFFFFFu, acc, off);
    const int lane = t & 31;
    const int wid  = t >> 5;
    if (lane == 0) warp_sums[wid] = acc;
    __syncthreads();

    if (t == 0) {
        float s0 = 0.0f;
        #pragma unroll
        for (int i = 0; i < 8; i++) s0 += warp_sums[i];
        if (s0 != 0.0f || cnt) {
            atomicAdd(&g_loss_acc, s0);
            atomicAdd(&g_mask_cnt, cnt);
        }
        finalize_and_reset(out, S, NB);
    }
}

// ---------------- generic fallback: one pair per 128-thread block ------------
__global__ void __launch_bounds__(128) ml_fused_kernel(
    const float* __restrict__ shape,
    const int*   __restrict__ mask,
    const int*   __restrict__ ind,
    const float* __restrict__ target,
    float*       __restrict__ out,
    int C, int HW, int K, int S, int nBlocks)
{
    const int bk = blockIdx.x;
    const int t  = threadIdx.x;
    const int active = mask[bk];

    __shared__ float warp_sums[4];
    extern __shared__ float pred[];

    float blocksum = 0.0f;
    if (active) {
        const int b  = bk / K;
        const int hw = ind[bk];
        for (int c = t; c < C; c += blockDim.x)
            pred[c] = __ldg(&shape[(size_t)b * C * HW + (size_t)c * HW + hw]);
        __syncthreads();

        const float scale = (float)C / (float)S;
        const float cmax  = (float)(C - 1);
        const float* tg = target + (size_t)bk * S;

        float acc = 0.0f;
        for (int s = t; s < S; s += blockDim.x) {
            float pos = ((float)s + 0.5f) * scale - 0.5f;
            pos = fminf(fmaxf(pos, 0.0f), cmax);
            int lo = (int)pos;
            int hi = min(lo + 1, C - 1);
            float w = pos - (float)lo;
            acc += fabsf(pred[lo] * (1.0f - w) + pred[hi] * w - __ldg(&tg[s]));
        }
        #pragma unroll
        for (int off = 16; off > 0; off >>= 1)
            acc += __shfl_down_sync(0xFFFFFFFFu, acc, off);
        const int lane = t & 31, wid = t >> 5;
        if (lane == 0) warp_sums[wid] = acc;
        __syncthreads();
        if (t == 0)
            blocksum = warp_sums[0] + warp_sums[1] + warp_sums[2] + warp_sums[3];
    }

    if (t == 0) {
        if (active) {
            atomicAdd(&g_loss_acc, blocksum);
            atomicAdd(&g_mask_cnt, 1);
        }
        finalize_and_reset(out, S, nBlocks);
    }
}

extern "C" void kernel_launch(void* const* d_in, const int* in_sizes, int n_in,
                              void* d_out, int out_size)
{
    const float* shape  = (const float*)d_in[0];
    const int*   mask   = (const int*)  d_in[3];
    const int*   ind    = (const int*)  d_in[4];
    const float* target = (const float*)d_in[5];
    float* out = (float*)d_out;

    const int B   = 16;
    const int C   = in_sizes[0] / in_sizes[2];   // shape / saliency = C
    const int HW  = in_sizes[2] / B;             // saliency = B*HW
    const int K   = in_sizes[3] / B;             // mask = B*K
    const int S   = in_sizes[5] / in_sizes[3];   // target / mask = S

    const int nPairs = B * K;

    if (C == 128 && S == 1024 && (nPairs % 4) == 0) {
        const int G  = nPairs / 4;               // groups of 4 pairs
        int NB = 256;                            // resident blocks (single wave)
        if (NB > G) NB = G;
        ml_persist_kernel<<<NB, 256>>>(shape, mask, ind, target, out, HW, K, G);
    } else {
        const size_t smem = (size_t)C * sizeof(float);
        ml_fused_kernel<<<nPairs, 128, smem>>>(shape, mask, ind, target, out,
                                               C, HW, K, S, nPairs);
    }
}

// round 16
// speedup vs baseline: 1.4090x; 1.4090x over previous
#include <cuda_runtime.h>
#include <cuda_bf16.h>

// Inputs (metadata order):
//   0: shape    float32 [B, C, H, W]       B=16, C=128, H=W=128
//   1: size     int32   scalar (S=1024)
//   2: saliency float32 [B, 1, H, W]       (unused)
//   3: mask     int32   [B, K]             K=256
//   4: ind      int32   [B, K]
//   5: target   float32 [B, K, S]
// Output: float32 [1] = sum(|pred*m - target*m|) / (sum(m)*S + 1e-4)
//
// Warp-per-pair design: each warp owns one (b,k) pair. Every lane issues
// 12 independent global loads up front (8 coalesced target float4s + 4
// gather floats); the gathered channel vector is staged in a per-warp smem
// slice (warp-synchronous, no __syncthreads in the hot path). Inactive
// warps retire immediately. One atomic set + completion ticket per block.

__device__ float        g_loss_acc;   // zero-init; reset by last block
__device__ int          g_mask_cnt;
__device__ unsigned int g_done;

__device__ __forceinline__ void finalize_and_reset(float* __restrict__ out,
                                                   int S, int nBlocks)
{
    __threadfence();
    unsigned int ticket = atomicAdd(&g_done, 1u);
    if (ticket == (unsigned int)(nBlocks - 1)) {
        float total = atomicAdd(&g_loss_acc, 0.0f);
        int   cnt   = atomicAdd(&g_mask_cnt, 0);
        out[0] = total / ((float)cnt * (float)S + 1e-4f);
        g_loss_acc = 0.0f;
        g_mask_cnt = 0;
        __threadfence();
        g_done = 0u;
    }
}

// ---------------- specialized: C=128, S=1024, warp-per-pair ----------------
__global__ void __launch_bounds__(256) ml_warp_kernel(
    const float* __restrict__ shape,   // [B, C, HW]
    const int*   __restrict__ mask,    // [B*K]
    const int*   __restrict__ ind,     // [B*K]
    const float* __restrict__ target,  // [B*K, S]
    float*       __restrict__ out,
    int HW, int K, int nBlocks)
{
    constexpr int C = 128, S = 1024;
    constexpr int WARPS = 8;           // per block
    const int t    = threadIdx.x;
    const int lane = t & 31;
    const int w    = t >> 5;           // warp id in block
    const int bk   = blockIdx.x * WARPS + w;   // one pair per warp

    __shared__ float pred[WARPS][C];   // per-warp slice: 512B each
    __shared__ float warp_sums[WARPS];
    __shared__ int   warp_cnt[WARPS];

    const int m = mask[bk];
    float acc = 0.0f;

    if (m) {
        // ---- issue ALL 12 independent loads up front ----
        // 8 coalesced target float4s: lane L owns quads q = L + 32*i.
        const float4* __restrict__ tg4 = (const float4*)(target + (size_t)bk * S);
        float4 tv[8];
        #pragma unroll
        for (int i = 0; i < 8; i++)
            tv[i] = __ldg(&tg4[lane + 32 * i]);

        // 4 gather loads: lane L owns channels 4L..4L+3 (HW-strided).
        const int b  = bk / K;
        const int hw = ind[bk];        // broadcast load (uniform in warp)
        const float* __restrict__ sp = shape + (size_t)b * C * HW + hw;
        float gv[4];
        #pragma unroll
        for (int j = 0; j < 4; j++)
            gv[j] = __ldg(&sp[(size_t)(4 * lane + j) * HW]);

        // Stage gathers in this warp's smem slice (warp-synchronous).
        #pragma unroll
        for (int j = 0; j < 4; j++)
            pred[w][4 * lane + j] = gv[j];
        __syncwarp();

        // ---- compute: 32 s-positions per lane ----
        const float scale = (float)C / (float)S;   // 0.125
        const float cmax  = (float)(C - 1);
        const float* pr = pred[w];
        #pragma unroll
        for (int i = 0; i < 8; i++) {
            const int s0 = 4 * (lane + 32 * i);
            #pragma unroll
            for (int j = 0; j < 4; j++) {
                float pos = ((float)(s0 + j) + 0.5f) * scale - 0.5f;
                pos = fminf(fmaxf(pos, 0.0f), cmax);
                int lo = (int)pos;
                int hi = min(lo + 1, C - 1);
                float ww = pos - (float)lo;
                float v = pr[lo] * (1.0f - ww) + pr[hi] * ww;
                float tj = (j == 0) ? tv[i].x : (j == 1) ? tv[i].y
                         : (j == 2) ? tv[i].z : tv[i].w;
                acc += fabsf(v - tj);
            }
        }
    }

    // ---- warp reduce, then one atomic set per block ----
    #pragma unroll
    for (int off = 16; off > 0; off >>= 1)
        acc += __shfl_down_sync(0xFFFFFFFFu, acc, off);
    if (lane == 0) { warp_sums[w] = acc; warp_cnt[w] = m ? 1 : 0; }
    __syncthreads();

    if (t == 0) {
        float s0 = 0.0f; int cnt = 0;
        #pragma unroll
        for (int i = 0; i < WARPS; i++) { s0 += warp_sums[i]; cnt += warp_cnt[i]; }
        if (s0 != 0.0f || cnt) {
            atomicAdd(&g_loss_acc, s0);
            atomicAdd(&g_mask_cnt, cnt);
        }
        finalize_and_reset(out, S, nBlocks);
    }
}

// ---------------- generic fallback: one pair per 128-thread block ------------
__global__ void __launch_bounds__(128) ml_fused_kernel(
    const float* __restrict__ shape,
    const int*   __restrict__ mask,
    const int*   __restrict__ ind,
    const float* __restrict__ target,
    float*       __restrict__ out,
    int C, int HW, int K, int S, int nBlocks)
{
    const int bk = blockIdx.x;
    const int t  = threadIdx.x;
    const int active = mask[bk];

    __shared__ float warp_sums[4];
    extern __shared__ float pred[];

    float blocksum = 0.0f;
    if (active) {
        const int b  = bk / K;
        const int hw = ind[bk];
        for (int c = t; c < C; c += blockDim.x)
            pred[c] = __ldg(&shape[(size_t)b * C * HW + (size_t)c * HW + hw]);
        __syncthreads();

        const float scale = (float)C / (float)S;
        const float cmax  = (float)(C - 1);
        const float* tg = target + (size_t)bk * S;

        float acc = 0.0f;
        for (int s = t; s < S; s += blockDim.x) {
            float pos = ((float)s + 0.5f) * scale - 0.5f;
            pos = fminf(fmaxf(pos, 0.0f), cmax);
            int lo = (int)pos;
            int hi = min(lo + 1, C - 1);
            float w = pos - (float)lo;
            acc += fabsf(pred[lo] * (1.0f - w) + pred[hi] * w - __ldg(&tg[s]));
        }
        #pragma unroll
        for (int off = 16; off > 0; off >>= 1)
            acc += __shfl_down_sync(0xFFFFFFFFu, acc, off);
        const int lane = t & 31, wid = t >> 5;
        if (lane == 0) warp_sums[wid] = acc;
        __syncthreads();
        if (t == 0)
            blocksum = warp_sums[0] + warp_sums[1] + warp_sums[2] + warp_sums[3];
    }

    if (t == 0) {
        if (active) {
            atomicAdd(&g_loss_acc, blocksum);
            atomicAdd(&g_mask_cnt, 1);
        }
        finalize_and_reset(out, S, nBlocks);
    }
}

extern "C" void kernel_launch(void* const* d_in, const int* in_sizes, int n_in,
                              void* d_out, int out_size)
{
    const float* shape  = (const float*)d_in[0];
    const int*   mask   = (const int*)  d_in[3];
    const int*   ind    = (const int*)  d_in[4];
    const float* target = (const float*)d_in[5];
    float* out = (float*)d_out;

    const int B   = 16;
    const int C   = in_sizes[0] / in_sizes[2];   // shape / saliency = C
    const int HW  = in_sizes[2] / B;             // saliency = B*HW
    const int K   = in_sizes[3] / B;             // mask = B*K
    const int S   = in_sizes[5] / in_sizes[3];   // target / mask = S

    const int nPairs = B * K;

    if (C == 128 && S == 1024 && (nPairs % 8) == 0) {
        const int nBlocks = nPairs / 8;          // 8 warps/block, 1 pair/warp
        ml_warp_kernel<<<nBlocks, 256>>>(shape, mask, ind, target, out,
                                         HW, K, nBlocks);
    } else {
        const size_t smem = (size_t)C * sizeof(float);
        ml_fused_kernel<<<nPairs, 128, smem>>>(shape, mask, ind, target, out,
                                               C, HW, K, S, nPairs);
    }
}